// round 7
// baseline (speedup 1.0000x reference)
#include <cuda_runtime.h>
#include <cuda_bf16.h>
#include <cuda_fp16.h>
#include <math.h>
#include <stdint.h>

#define N_NODES 100000
#define NPAD    100096
#define N_EDGES 3200000
#define NP1     100001
#define NSCAN_BLOCKS 98

#define LDAB 264                     // A smem row: [hi 0..127 | lo 128..255 | pad]
#define A_BYTES (128 * LDAB * 2)     // 67584
#define WT_TILE_BYTES 65536          // packed B tile: 16 nb x 8 ks x 512B

// ======================= device scratch =======================
__device__ int    g_rowptr[NP1];
__device__ int    g_bsum[128];
__device__ int    g_pos[N_NODES];
__device__ int    g_ecol[N_EDGES];
__device__ float  g_eval[N_EDGES];
__device__ float  g_h0[(size_t)NPAD * 128];
__device__ float  g_h1[(size_t)NPAD * 128];
__device__ __half g_supn[(size_t)NPAD * 128];
__device__ float  g_self[(size_t)NPAD * 128];
__device__ __nv_bfloat16 g_wt[9 * 32768];   // 9 x 64KB packed tiles

// ======================= helpers =======================
__device__ __forceinline__ uint32_t smem_u32(const void* p) {
    uint32_t a;
    asm("{ .reg .u64 t; cvta.to.shared.u64 t, %1; cvt.u32.u64 %0, t; }" : "=r"(a) : "l"(p));
    return a;
}
__device__ __forceinline__ void ldsm_x4(unsigned* r, uint32_t addr) {
    asm volatile("ldmatrix.sync.aligned.m8n8.x4.shared.b16 {%0,%1,%2,%3}, [%4];"
        : "=r"(r[0]), "=r"(r[1]), "=r"(r[2]), "=r"(r[3]) : "r"(addr));
}
__device__ __forceinline__ void mma_bf16(float* c, const unsigned* a, unsigned b0, unsigned b1) {
    asm volatile("mma.sync.aligned.m16n8k16.row.col.f32.bf16.bf16.f32 "
        "{%0,%1,%2,%3}, {%4,%5,%6,%7}, {%8,%9}, {%0,%1,%2,%3};"
        : "+f"(c[0]), "+f"(c[1]), "+f"(c[2]), "+f"(c[3])
        : "r"(a[0]), "r"(a[1]), "r"(a[2]), "r"(a[3]), "r"(b0), "r"(b1));
}

// ======================= CSR build =======================
__global__ void k_zero_rowptr() {
    int i = blockIdx.x * blockDim.x + threadIdx.x;
    if (i < NP1) g_rowptr[i] = 0;
}
__global__ void k_hist(const int* __restrict__ rows) {
    int e = blockIdx.x * blockDim.x + threadIdx.x;
    if (e < N_EDGES) atomicAdd(&g_rowptr[rows[e] + 1], 1);
}
__global__ void k_scan1() {
    __shared__ int s[1024];
    int t = threadIdx.x, i = blockIdx.x * 1024 + t;
    int v = (i < NP1) ? g_rowptr[i] : 0;
    s[t] = v; __syncthreads();
    #pragma unroll
    for (int off = 1; off < 1024; off <<= 1) {
        int tv = 0;
        if (t >= off) tv = s[t - off];
        __syncthreads(); s[t] += tv; __syncthreads();
    }
    if (i < NP1) g_rowptr[i] = s[t];
    if (t == 1023) g_bsum[blockIdx.x] = s[1023];
}
__global__ void k_scan2() {
    int acc = 0;
    for (int b = 0; b < NSCAN_BLOCKS; b++) { acc += g_bsum[b]; g_bsum[b] = acc; }
}
__global__ void k_scan3() {   // also writes g_pos
    int b = blockIdx.x;
    int i = b * 1024 + threadIdx.x;
    int add = b ? g_bsum[b - 1] : 0;
    if (i < NP1) {
        int v = g_rowptr[i] + add;
        g_rowptr[i] = v;
        if (i < N_NODES) g_pos[i] = v;
    }
}
__global__ void k_fill(const int* __restrict__ rows, const int* __restrict__ cols,
                       const float* __restrict__ vals) {
    int e = blockIdx.x * blockDim.x + threadIdx.x;
    if (e >= N_EDGES) return;
    int r = rows[e];
    int p = atomicAdd(&g_pos[r], 1);
    g_ecol[p] = cols[e];
    g_eval[p] = vals[e];
}

// ======================= weight prep: pack B in mma-fragment order ==============
__global__ void k_wprep(const float* __restrict__ fc1w, const float* __restrict__ fc2w,
                        const float* __restrict__ w0n, const float* __restrict__ w0s,
                        const float* __restrict__ w1n, const float* __restrict__ w1s,
                        const float* __restrict__ w2n, const float* __restrict__ w2s,
                        const float* __restrict__ w3n, const float* __restrict__ w3s,
                        __nv_bfloat16* __restrict__ wt)
{
    int t = blockIdx.y, n = blockIdx.x, k = threadIdx.x;
    float v;
    switch (t) {
        case 0: v = fc1w[n * 128 + k]; break;
        case 1: v = fc2w[n * 128 + k]; break;
        case 2: v = w0n[k * 128 + n]; break;
        case 3: v = w0s[k * 128 + n]; break;
        case 4: v = w1n[k * 128 + n]; break;
        case 5: v = w1s[k * 128 + n]; break;
        case 6: v = w2n[k * 128 + n]; break;
        case 7: v = w2s[k * 128 + n]; break;
        default: v = (n < 64) ? w3n[k * 64 + n] : w3s[k * 64 + (n - 64)]; break;
    }
    __nv_bfloat16 hi = __float2bfloat16_rn(v);
    __nv_bfloat16 lo = __float2bfloat16_rn(v - __bfloat162float(hi));

    int ks = k >> 4, kk = k & 15;
    int q, e;
    if (kk < 8) { q = kk >> 1; e = kk & 1; }
    else        { q = (kk - 8) >> 1; e = 2 + (kk & 1); }
    int nb = n >> 3, n7 = n & 7;
    char* base = (char*)wt + (size_t)t * WT_TILE_BYTES
               + ((nb * 8 + ks) * 512) + n7 * 64 + q * 16;
    *(__nv_bfloat16*)(base + e * 2)     = hi;
    *(__nv_bfloat16*)(base + 8 + e * 2) = lo;
}

// ======================= mma.sync bf16 GEMM (3-term, SW-pipelined) ==============
__global__ __launch_bounds__(256, 2) void k_mm(
    const float* __restrict__ X,
    const __nv_bfloat16* __restrict__ Bw,
    const float* __restrict__ bias,
    void* __restrict__ o0, int m0,
    void* __restrict__ o1, int m1,
    int nH)
{
    extern __shared__ __nv_bfloat16 As[];   // 128 x LDAB

    const int tid = threadIdx.x, wid = tid >> 5, lane = tid & 31;
    const int wm = wid >> 2, wn = wid & 3;   // warp tile: 64 rows x 32 cols
    const int row0 = blockIdx.x * 128;

    // ---- load A tile, split fp32 -> bf16 hi/lo ----
    #pragma unroll
    for (int it = 0; it < 16; it++) {
        int idx = tid + 256 * it;
        int r = idx >> 5, c4 = idx & 31;
        float4 v = make_float4(0.f, 0.f, 0.f, 0.f);
        int row = row0 + r;
        if (row < N_NODES) v = *(const float4*)&X[(size_t)row * 128 + c4 * 4];
        __nv_bfloat16 hx = __float2bfloat16_rn(v.x);
        __nv_bfloat16 hy = __float2bfloat16_rn(v.y);
        __nv_bfloat16 hz = __float2bfloat16_rn(v.z);
        __nv_bfloat16 hw = __float2bfloat16_rn(v.w);
        __nv_bfloat16 lx = __float2bfloat16_rn(v.x - __bfloat162float(hx));
        __nv_bfloat16 ly = __float2bfloat16_rn(v.y - __bfloat162float(hy));
        __nv_bfloat16 lz = __float2bfloat16_rn(v.z - __bfloat162float(hz));
        __nv_bfloat16 lw = __float2bfloat16_rn(v.w - __bfloat162float(hw));
        __nv_bfloat16* ap = As + r * LDAB + c4 * 4;
        *(__nv_bfloat162*)(ap + 0)   = __halves2bfloat162(hx, hy);
        *(__nv_bfloat162*)(ap + 2)   = __halves2bfloat162(hz, hw);
        *(__nv_bfloat162*)(ap + 128) = __halves2bfloat162(lx, ly);
        *(__nv_bfloat162*)(ap + 130) = __halves2bfloat162(lz, lw);
    }
    __syncthreads();

    const uint32_t aBase = smem_u32(As) +
        2u * (uint32_t)((wm * 64 + (lane & 15)) * LDAB + ((lane >> 4) << 3));
    const char* bLane = (const char*)Bw + (lane >> 2) * 64 + (lane & 3) * 16;

    for (int nh = 0; nh < nH; nh++) {
        const char* Bt = bLane + (size_t)nh * WT_TILE_BYTES;

        float acc[4][4][4];
        #pragma unroll
        for (int i = 0; i < 4; i++)
            #pragma unroll
            for (int j = 0; j < 4; j++)
                #pragma unroll
                for (int q = 0; q < 4; q++) acc[i][j][q] = 0.f;

        // prime B double-buffer with ks=0
        uint4 bcur[4];
        #pragma unroll
        for (int j = 0; j < 4; j++)
            bcur[j] = *(const uint4*)(Bt + ((wn * 4 + j) * 8 + 0) * 512);

        #pragma unroll
        for (int ks = 0; ks < 8; ks++) {
            const int ka = ks * 16;
            // prefetch next ks (clamped; latency hidden behind 48 MMAs)
            uint4 bnext[4];
            const int ksn = (ks < 7) ? ks + 1 : 7;
            #pragma unroll
            for (int j = 0; j < 4; j++)
                bnext[j] = *(const uint4*)(Bt + ((wn * 4 + j) * 8 + ksn) * 512);

            unsigned af[4][4];
            // A-hi pass: AhBh then AhBl
            #pragma unroll
            for (int i = 0; i < 4; i++)
                ldsm_x4(af[i], aBase + 2u * (uint32_t)(i * 16 * LDAB + ka));
            #pragma unroll
            for (int i = 0; i < 4; i++)
                #pragma unroll
                for (int j = 0; j < 4; j++)
                    mma_bf16(acc[i][j], af[i], bcur[j].x, bcur[j].y);
            #pragma unroll
            for (int i = 0; i < 4; i++)
                #pragma unroll
                for (int j = 0; j < 4; j++)
                    mma_bf16(acc[i][j], af[i], bcur[j].z, bcur[j].w);
            // A-lo pass (af regs reused): AlBh
            #pragma unroll
            for (int i = 0; i < 4; i++)
                ldsm_x4(af[i], aBase + 2u * (uint32_t)(i * 16 * LDAB + ka + 128));
            #pragma unroll
            for (int i = 0; i < 4; i++)
                #pragma unroll
                for (int j = 0; j < 4; j++)
                    mma_bf16(acc[i][j], af[i], bcur[j].x, bcur[j].y);

            #pragma unroll
            for (int j = 0; j < 4; j++) bcur[j] = bnext[j];
        }

        // ---- register epilogue (outputs NPAD-padded: no row guard) ----
        const int mode = (nh == 0) ? m0 : m1;
        const int cb = wn * 32 + 2 * (lane & 3);
        const int rb = row0 + wm * 64 + (lane >> 2);

        if (mode == 0) {
            float2 bvv[4];
            #pragma unroll
            for (int j = 0; j < 4; j++) bvv[j] = *(const float2*)&bias[cb + j * 8];
            float* out = (float*)o0;
            #pragma unroll
            for (int i = 0; i < 4; i++) {
                size_t r1 = (size_t)(rb + i * 16) * 128;
                size_t r2 = r1 + 8 * 128;
                #pragma unroll
                for (int j = 0; j < 4; j++) {
                    float* a = acc[i][j];
                    int c = cb + j * 8;
                    *(float2*)&out[r1 + c] = make_float2(fmaxf(a[0] + bvv[j].x, 0.f),
                                                         fmaxf(a[1] + bvv[j].y, 0.f));
                    *(float2*)&out[r2 + c] = make_float2(fmaxf(a[2] + bvv[j].x, 0.f),
                                                         fmaxf(a[3] + bvv[j].y, 0.f));
                }
            }
        } else if (mode == 1) {
            __half* out = (__half*)o0;
            #pragma unroll
            for (int i = 0; i < 4; i++) {
                size_t r1 = (size_t)(rb + i * 16) * 128;
                size_t r2 = r1 + 8 * 128;
                #pragma unroll
                for (int j = 0; j < 4; j++) {
                    float* a = acc[i][j];
                    int c = cb + j * 8;
                    *(__half2*)&out[r1 + c] = __floats2half2_rn(a[0], a[1]);
                    *(__half2*)&out[r2 + c] = __floats2half2_rn(a[2], a[3]);
                }
            }
        } else if (mode == 2) {
            float* out = (float*)o1;
            #pragma unroll
            for (int i = 0; i < 4; i++) {
                size_t r1 = (size_t)(rb + i * 16) * 128;
                size_t r2 = r1 + 8 * 128;
                #pragma unroll
                for (int j = 0; j < 4; j++) {
                    float* a = acc[i][j];
                    int c = cb + j * 8;
                    *(float2*)&out[r1 + c] = make_float2(a[0], a[1]);
                    *(float2*)&out[r2 + c] = make_float2(a[2], a[3]);
                }
            }
        } else {   // mode 3: cols<64 -> fp16 o0 (ld64); cols>=64 -> f32 o1 (ld64)
            if (wn < 2) {
                __half* out = (__half*)o0;
                #pragma unroll
                for (int i = 0; i < 4; i++) {
                    size_t r1 = (size_t)(rb + i * 16) * 64;
                    size_t r2 = r1 + 8 * 64;
                    #pragma unroll
                    for (int j = 0; j < 4; j++) {
                        float* a = acc[i][j];
                        int c = cb + j * 8;
                        *(__half2*)&out[r1 + c] = __floats2half2_rn(a[0], a[1]);
                        *(__half2*)&out[r2 + c] = __floats2half2_rn(a[2], a[3]);
                    }
                }
            } else {
                float* out = (float*)o1;
                #pragma unroll
                for (int i = 0; i < 4; i++) {
                    size_t r1 = (size_t)(rb + i * 16) * 64;
                    size_t r2 = r1 + 8 * 64;
                    #pragma unroll
                    for (int j = 0; j < 4; j++) {
                        float* a = acc[i][j];
                        int c = cb + j * 8 - 64;
                        *(float2*)&out[r1 + c] = make_float2(a[0], a[1]);
                        *(float2*)&out[r2 + c] = make_float2(a[2], a[3]);
                    }
                }
            }
        }
    }
}

// ======================= LayerNorm =======================
__global__ __launch_bounds__(256) void k_ln(const float* __restrict__ in,
                                            float* __restrict__ out,
                                            const float* __restrict__ g,
                                            const float* __restrict__ b)
{
    int row  = blockIdx.x * 8 + (threadIdx.x >> 5);
    int lane = threadIdx.x & 31;
    float4 v = *(const float4*)&in[(size_t)row * 128 + lane * 4];
    float s = v.x + v.y + v.z + v.w;
    #pragma unroll
    for (int o = 16; o; o >>= 1) s += __shfl_xor_sync(0xffffffffu, s, o);
    float mean = s * (1.f / 128.f);
    float dx = v.x - mean, dy = v.y - mean, dz = v.z - mean, dw = v.w - mean;
    float ss = dx*dx + dy*dy + dz*dz + dw*dw;
    #pragma unroll
    for (int o = 16; o; o >>= 1) ss += __shfl_xor_sync(0xffffffffu, ss, o);
    float inv = 1.f / (sqrtf(ss * (1.f / 127.f)) + 1e-6f);
    float4 gg = *(const float4*)&g[lane * 4];
    float4 bb = *(const float4*)&b[lane * 4];
    float4 o4;
    o4.x = gg.x * dx * inv + bb.x;
    o4.y = gg.y * dy * inv + bb.y;
    o4.z = gg.z * dz * inv + bb.z;
    o4.w = gg.w * dw * inv + bb.w;
    *(float4*)&out[(size_t)row * 128 + lane * 4] = o4;
}

// ======================= GCN aggregate (fp16 gather) =======================
template <int OUT>
__global__ __launch_bounds__(256) void k_agg(const __half* __restrict__ supn,
                                             const float* __restrict__ selfm,
                                             const float* __restrict__ bias,
                                             float* __restrict__ out)
{
    const int V = OUT / 32;
    int node = blockIdx.x * 8 + (threadIdx.x >> 5);
    int lane = threadIdx.x & 31;

    float acc[V];
    {
        const float* sr = selfm + (size_t)node * OUT + lane * V;
        #pragma unroll
        for (int i = 0; i < V; i++) acc[i] = sr[i] + bias[lane * V + i];
    }

    int e0 = g_rowptr[node], e1 = g_rowptr[node + 1];
    for (int eb = e0; eb < e1; eb += 32) {
        int rem = e1 - eb;
        int c = 0; float wv = 0.f;
        if (lane < rem) { c = g_ecol[eb + lane]; wv = g_eval[eb + lane]; }
        if (rem >= 32) {
            #pragma unroll 8
            for (int j = 0; j < 32; j++) {
                int   cj = __shfl_sync(0xffffffffu, c, j);
                float wj = __shfl_sync(0xffffffffu, wv, j);
                const __half* srow = supn + (size_t)cj * OUT + lane * V;
                if (V == 4) {
                    uint2 u = *(const uint2*)srow;
                    float2 f0 = __half22float2(*(const __half2*)&u.x);
                    float2 f1 = __half22float2(*(const __half2*)&u.y);
                    acc[0] = fmaf(wj, f0.x, acc[0]);
                    acc[1] = fmaf(wj, f0.y, acc[1]);
                    acc[2] = fmaf(wj, f1.x, acc[2]);
                    acc[3] = fmaf(wj, f1.y, acc[3]);
                } else {
                    uint32_t u = *(const uint32_t*)srow;
                    float2 f0 = __half22float2(*(const __half2*)&u);
                    acc[0] = fmaf(wj, f0.x, acc[0]);
                    acc[1] = fmaf(wj, f0.y, acc[1]);
                }
            }
        } else {
            for (int j = 0; j < rem; j++) {
                int   cj = __shfl_sync(0xffffffffu, c, j);
                float wj = __shfl_sync(0xffffffffu, wv, j);
                const __half* srow = supn + (size_t)cj * OUT + lane * V;
                if (V == 4) {
                    uint2 u = *(const uint2*)srow;
                    float2 f0 = __half22float2(*(const __half2*)&u.x);
                    float2 f1 = __half22float2(*(const __half2*)&u.y);
                    acc[0] = fmaf(wj, f0.x, acc[0]);
                    acc[1] = fmaf(wj, f0.y, acc[1]);
                    acc[2] = fmaf(wj, f1.x, acc[2]);
                    acc[3] = fmaf(wj, f1.y, acc[3]);
                } else {
                    uint32_t u = *(const uint32_t*)srow;
                    float2 f0 = __half22float2(*(const __half2*)&u);
                    acc[0] = fmaf(wj, f0.x, acc[0]);
                    acc[1] = fmaf(wj, f0.y, acc[1]);
                }
            }
        }
    }

    float* orow = out + (size_t)node * OUT + lane * V;
    #pragma unroll
    for (int i = 0; i < V; i++) orow[i] = fmaxf(acc[i], 0.f);
}

// ======================= launch =======================
extern "C" void kernel_launch(void* const* d_in, const int* in_sizes, int n_in,
                              void* d_out, int out_size)
{
    const float* x    = (const float*)d_in[0];
    const int*   er   = (const int*)d_in[1];
    const int*   ec   = (const int*)d_in[2];
    const float* ev   = (const float*)d_in[3];
    const float* fc1w = (const float*)d_in[4];
    const float* fc1b = (const float*)d_in[5];
    const float* fc2w = (const float*)d_in[6];
    const float* fc2b = (const float*)d_in[7];
    const float* lng  = (const float*)d_in[8];
    const float* lnb  = (const float*)d_in[9];
    const float *wn[4], *wsf[4], *gb[4];
    for (int i = 0; i < 4; i++) {
        wn[i]  = (const float*)d_in[10 + 3 * i];
        wsf[i] = (const float*)d_in[11 + 3 * i];
        gb[i]  = (const float*)d_in[12 + 3 * i];
    }
    float* outp = (float*)d_out;

    float *h0, *h1, *selfb;
    __half* supn;
    __nv_bfloat16* wt;
    cudaGetSymbolAddress((void**)&h0,    g_h0);
    cudaGetSymbolAddress((void**)&h1,    g_h1);
    cudaGetSymbolAddress((void**)&supn,  g_supn);
    cudaGetSymbolAddress((void**)&selfb, g_self);
    cudaGetSymbolAddress((void**)&wt,    g_wt);
    auto WT = [&](int t) { return wt + (size_t)t * 32768; };

    const int SMEM = A_BYTES;
    cudaFuncSetAttribute(k_mm, cudaFuncAttributeMaxDynamicSharedMemorySize, SMEM);

    const int MT = (N_NODES + 127) / 128;   // 782

    k_wprep<<<dim3(128, 9), 128>>>(fc1w, fc2w, wn[0], wsf[0], wn[1], wsf[1],
                                   wn[2], wsf[2], wn[3], wsf[3], wt);           // 0
    k_zero_rowptr<<<(NP1 + 255) / 256, 256>>>();                                 // 1
    k_hist<<<(N_EDGES + 255) / 256, 256>>>(er);                                  // 2
    k_mm<<<MT, 256, SMEM>>>(x, WT(0), fc1b, h0, 0, nullptr, 0, 1);               // 3 <- profiled
    k_scan1<<<NSCAN_BLOCKS, 1024>>>();                                           // 4
    k_scan2<<<1, 1>>>();                                                         // 5
    k_scan3<<<NSCAN_BLOCKS, 1024>>>();                                           // 6
    k_fill<<<(N_EDGES + 255) / 256, 256>>>(er, ec, ev);                          // 7
    k_mm<<<MT, 256, SMEM>>>(h0, WT(1), fc2b, h1, 0, nullptr, 0, 1);              // 8
    k_ln<<<N_NODES / 8, 256>>>(h1, h0, lng, lnb);                                // 9

    float* cur = h0;
    float* nxt = h1;
    for (int l = 0; l < 3; l++) {
        k_mm<<<MT, 256, SMEM>>>(cur, WT(2 + 2 * l), nullptr, supn, 1, selfb, 2, 2);
        k_agg<128><<<N_NODES / 8, 256>>>(supn, selfb, gb[l], nxt);
        float* t = cur; cur = nxt; nxt = t;
    }

    k_mm<<<MT, 256, SMEM>>>(cur, WT(8), nullptr, supn, 3, selfb, 3, 1);
    k_agg<64><<<N_NODES / 8, 256>>>(supn, selfb, gb[3], outp);
}